// round 12
// baseline (speedup 1.0000x reference)
#include <cuda_runtime.h>
#include <cuda_bf16.h>

typedef unsigned long long ull;

// Problem constants (fixed by the dataset)
#define N_NODES 16384      // B*n = 8*2048
#define K_EDGE  16
#define CIN     64
#define HID     64
#define OUTC    128
#define L6      6
#define KV      384        // 6*64
#define EPS     1e-5f

// ---------------- scratch (device globals; no allocations) ----------------
__device__ float g_V[N_NODES * KV];        // [t][l*64+c]
__device__ float g_Cl[N_NODES * L6];       // per-target coefficient sums
__device__ float g_Y[N_NODES * HID];       // y_pre (before BN1)
__device__ float g_part1[2 * 128 * HID];   // per-k2-block BN partials (sum, sumsq)
__device__ float g_part2[2 * 128 * OUTC];  // per-k4-block BN partials
__device__ float g_bn1[2 * HID];           // folded scale/shift for BN1
__device__ float g_bn2[2 * OUTC];          // folded scale/shift for BN2
__device__ int   g_cnt1, g_cnt2;           // last-block-done counters

// ---------------- helpers ----------------
__device__ __forceinline__ void ffma2(ull& d, ull a, ull b) {
    asm("fma.rn.f32x2 %0, %1, %2, %3;" : "=l"(d) : "l"(a), "l"(b), "l"(d));
}
__device__ __forceinline__ ull dup2(float v) {
    ull r; asm("mov.b64 %0, {%1, %1};" : "=l"(r) : "f"(v)); return r;
}
__device__ __forceinline__ float2 unpk(ull v) {
    float2 r; asm("mov.b64 {%0, %1}, %2;" : "=f"(r.x), "=f"(r.y) : "l"(v)); return r;
}
__device__ __forceinline__ void cp4(void* smem_dst, const void* gsrc) {
    unsigned d = (unsigned)__cvta_generic_to_shared(smem_dst);
    asm volatile("cp.async.ca.shared.global [%0], [%1], 4;" :: "r"(d), "l"(gsrc));
}
__device__ __forceinline__ void cp_commit() { asm volatile("cp.async.commit_group;"); }
__device__ __forceinline__ void cp_wait0()  { asm volatile("cp.async.wait_group 0;" ::: "memory"); }

// ---------------- K1: per-target edge phase (proven) ----------------
// grid = N_NODES/4 blocks, 256 threads (4 targets per block).
__global__ __launch_bounds__(256) void k1_edge(
    const float* __restrict__ x, const float* __restrict__ p,
    const int* __restrict__ sid)
{
    __shared__ float s_coef[4][K_EDGE][8];
    __shared__ int   s_sid[4][K_EDGE];

    const int tid  = threadIdx.x;
    const int w    = tid >> 5;
    const int lane = tid & 31;

    if (blockIdx.x == 0 && tid == 0) { g_cnt1 = 0; g_cnt2 = 0; }

    if (w < 4) {
        const int t   = blockIdx.x * 4 + w;
        const int j   = lane & 15;
        const bool act = lane < 16;
        const int s   = sid[t * K_EDGE + j];

        float dx = 0.f, dy = 0.f, dz = 0.f, dis = 0.f;
        if (act) {
            const float px = p[t*3+0], py = p[t*3+1], pz = p[t*3+2];
            dx = p[s*3+0] - px;
            dy = p[s*3+1] - py;
            dz = p[s*3+2] - pz;
            dis = fmaxf(sqrtf(dx*dx + dy*dy + dz*dz), 1e-16f);
            s_sid[w][j] = s;
        }
        float m = dis;
        #pragma unroll
        for (int off = 16; off; off >>= 1)
            m = fmaxf(m, __shfl_xor_sync(0xffffffffu, m, off));
        const float pr  = 1.1f * m;
        float pdv = act ? (pr - dis) * (pr - dis) : 0.f;
        float ssum = pdv;
        #pragma unroll
        for (int off = 16; off; off >>= 1)
            ssum += __shfl_xor_sync(0xffffffffu, ssum, off);

        if (act) {
            const float wgt = pdv / ssum;
            const float inv = 1.f / dis;
            const float c0 = cosf(dx * inv);
            const float c1 = cosf(dy * inv);
            const float c2 = cosf(dz * inv);
            float a[6] = {0.f, 0.f, 0.f, 0.f, 0.f, 0.f};
            a[    ((dx > 0.f) ? 1 : 0)] = c0 * c0;
            a[2 + ((dy > 0.f) ? 1 : 0)] = c1 * c1;
            a[4 + ((dz > 0.f) ? 1 : 0)] = c2 * c2;
            #pragma unroll
            for (int l = 0; l < 6; l++) s_coef[w][j][l] = wgt * a[l];
        }
    }
    __syncthreads();

    if (tid < 24) {
        const int tw = tid / 6, l = tid - tw * 6;
        float cl = 0.f;
        #pragma unroll
        for (int j = 0; j < K_EDGE; j++) cl += s_coef[tw][j][l];
        g_Cl[(blockIdx.x * 4 + tw) * L6 + l] = cl;
    }

    const int grp = tid >> 6;
    const int c   = tid & 63;
    const int t   = blockIdx.x * 4 + grp;
    const float xt = x[t * CIN + c];
    float acc[6] = {0.f, 0.f, 0.f, 0.f, 0.f, 0.f};
    #pragma unroll
    for (int j = 0; j < K_EDGE; j++) {
        const float ev = x[s_sid[grp][j] * CIN + c] - xt;
        const float4 c01 = *(const float4*)&s_coef[grp][j][0];
        const float2 c2  = *(const float2*)&s_coef[grp][j][4];
        acc[0] = fmaf(c01.x, ev, acc[0]);
        acc[1] = fmaf(c01.y, ev, acc[1]);
        acc[2] = fmaf(c01.z, ev, acc[2]);
        acc[3] = fmaf(c01.w, ev, acc[3]);
        acc[4] = fmaf(c2.x,  ev, acc[4]);
        acc[5] = fmaf(c2.y,  ev, acc[5]);
    }
    float* vp = g_V + (size_t)t * KV + c;
    #pragma unroll
    for (int l = 0; l < 6; l++) vp[l * 64] = acc[l];
}

// ---------------- K2: y_pre = V @ Wcat + Cl @ lins_b  (+ BN1 stats) --------
// BM=128, BN=64, BK=16, 512 threads (16 warps -> 4/SMSP), cp.async
// double-buffered, pair-over-M f32x2 (A natural m-contiguous: ull slot p =
// rows 2p,2p+1; in-warp reads are 2-address broadcasts). grid = 128.
__global__ __launch_bounds__(512) void k2_gemm(
    const float* __restrict__ W2,   // lins_W viewed as (384, 64)
    const float* __restrict__ lb,   // lins_b (6, 64)
    const float* __restrict__ gam1, const float* __restrict__ bet1)
{
    __shared__ float As[2][16 * 130];   // [st][kk*130 + m]
    __shared__ ull   Bd[2][16 * 64];    // dup pairs, slot (h&3)*16 + (h>>2)
    __shared__ float sb[6][64];
    __shared__ float s_m[16][64], s_v[16][64];
    __shared__ bool  s_last;

    const int tid = threadIdx.x;
    const int r0  = blockIdx.x * 128;
    for (int i = tid; i < 384; i += 512) sb[i >> 6][i & 63] = lb[i];

    const int tx  = tid & 15, ty = tid >> 4;     // ty 0..31: rows ty*4..ty*4+3
    const int lkk = tid & 15, lm0 = tid >> 4;    // A loader: 4 elems/thread
    const int bq  = tid >> 6, bh = tid & 63;     // B loader: 2 rows/thread
    const int bslot = (bh & 3) * 16 + (bh >> 2);

    #pragma unroll
    for (int jj = 0; jj < 4; jj++)
        cp4(&As[0][lkk * 130 + lm0 + 32 * jj],
            &g_V[(size_t)(r0 + lm0 + 32 * jj) * KV + lkk]);
    cp_commit();
    float rb[2];
    rb[0] = W2[bq * 64 + bh];
    rb[1] = W2[(bq + 8) * 64 + bh];
    Bd[0][bq * 64 + bslot]       = dup2(rb[0]);
    Bd[0][(bq + 8) * 64 + bslot] = dup2(rb[1]);
    cp_wait0();
    __syncthreads();

    ull acc[2][4];
    #pragma unroll
    for (int i = 0; i < 2; i++)
        #pragma unroll
        for (int j = 0; j < 4; j++) acc[i][j] = 0ULL;

    for (int s = 0; s < 24; s++) {
        const int st = s & 1;
        const bool more = (s < 23);
        if (more) {
            const int k0n = (s + 1) * 16;
            #pragma unroll
            for (int jj = 0; jj < 4; jj++)
                cp4(&As[st ^ 1][lkk * 130 + lm0 + 32 * jj],
                    &g_V[(size_t)(r0 + lm0 + 32 * jj) * KV + k0n + lkk]);
            cp_commit();
            rb[0] = W2[(k0n + bq) * 64 + bh];
            rb[1] = W2[(k0n + bq + 8) * 64 + bh];
        }
        #pragma unroll
        for (int kk = 0; kk < 16; kk++) {
            const ull* ap = (const ull*)&As[st][kk * 130];
            const ull* bp = &Bd[st][kk * 64];
            ull a0 = ap[ty * 2], a1 = ap[ty * 2 + 1];
            ull b0 = bp[tx], b1 = bp[16 + tx], b2 = bp[32 + tx], b3 = bp[48 + tx];
            ffma2(acc[0][0], a0, b0); ffma2(acc[0][1], a0, b1);
            ffma2(acc[0][2], a0, b2); ffma2(acc[0][3], a0, b3);
            ffma2(acc[1][0], a1, b0); ffma2(acc[1][1], a1, b1);
            ffma2(acc[1][2], a1, b2); ffma2(acc[1][3], a1, b3);
        }
        if (more) {
            Bd[st ^ 1][bq * 64 + bslot]       = dup2(rb[0]);
            Bd[st ^ 1][(bq + 8) * 64 + bslot] = dup2(rb[1]);
            cp_wait0();
        }
        __syncthreads();
    }

    // epilogue: + Cl@lins_b, store y_pre, BN1 partials
    // acc[pi][n] = (C[ty*4+2pi][tx*4+n], C[ty*4+2pi+1][tx*4+n])
    float cs[4] = {0.f, 0.f, 0.f, 0.f}, cs2[4] = {0.f, 0.f, 0.f, 0.f};
    #pragma unroll
    for (int pi = 0; pi < 2; pi++) {
        const int re = r0 + ty * 4 + 2 * pi;
        float2 v[4];
        #pragma unroll
        for (int n = 0; n < 4; n++) v[n] = unpk(acc[pi][n]);

        float cle[6], clo[6];
        #pragma unroll
        for (int l = 0; l < 6; l++) { cle[l] = g_Cl[re * L6 + l]; clo[l] = g_Cl[(re + 1) * L6 + l]; }

        float ve[4], vo[4];
        #pragma unroll
        for (int n = 0; n < 4; n++) {
            const int h = tx * 4 + n;
            float a = v[n].x, b = v[n].y;
            #pragma unroll
            for (int l = 0; l < 6; l++) {
                a = fmaf(cle[l], sb[l][h], a);
                b = fmaf(clo[l], sb[l][h], b);
            }
            ve[n] = a; vo[n] = b;
            cs[n]  += a + b;
            cs2[n] += a * a + b * b;
        }
        *(float4*)&g_Y[(size_t)re * HID + tx * 4] =
            make_float4(ve[0], ve[1], ve[2], ve[3]);
        *(float4*)&g_Y[(size_t)(re + 1) * HID + tx * 4] =
            make_float4(vo[0], vo[1], vo[2], vo[3]);
    }
    // merge lane l with lane l+16 (same tx, adjacent ty) then 16 warps store
    #pragma unroll
    for (int n = 0; n < 4; n++) {
        cs[n]  += __shfl_down_sync(0xffffffffu, cs[n], 16);
        cs2[n] += __shfl_down_sync(0xffffffffu, cs2[n], 16);
    }
    const int lane = tid & 31, wrp = tid >> 5;
    if (lane < 16) {
        #pragma unroll
        for (int n = 0; n < 4; n++) {
            s_m[wrp][lane * 4 + n] = cs[n];
            s_v[wrp][lane * 4 + n] = cs2[n];
        }
    }
    __syncthreads();
    if (tid < 64) {
        float s = 0.f, s2 = 0.f;
        #pragma unroll
        for (int g = 0; g < 16; g++) { s += s_m[g][tid]; s2 += s_v[g][tid]; }
        g_part1[blockIdx.x * 64 + tid] = s;
        g_part1[8192 + blockIdx.x * 64 + tid] = s2;
    }

    // last-block-done: fold BN1 stats
    __threadfence();
    if (tid == 0) s_last = (atomicAdd(&g_cnt1, 1) == (int)gridDim.x - 1);
    __syncthreads();
    if (s_last) {
        const int ch = tid & 63, q = tid >> 6;   // q = 0..7, 16 blocks each
        float s = 0.f, s2 = 0.f;
        #pragma unroll
        for (int b = q * 16; b < q * 16 + 16; b++) {
            s  += g_part1[b * 64 + ch];
            s2 += g_part1[8192 + b * 64 + ch];
        }
        s_m[q][ch] = s; s_v[q][ch] = s2;
        __syncthreads();
        if (tid < 64) {
            float ss = 0.f, ss2 = 0.f;
            #pragma unroll
            for (int g = 0; g < 8; g++) { ss += s_m[g][tid]; ss2 += s_v[g][tid]; }
            const float mean = ss * (1.f / (float)N_NODES);
            const float var  = ss2 * (1.f / (float)N_NODES) - mean * mean;
            const float sc = rsqrtf(var + EPS) * gam1[tid];
            g_bn1[tid] = sc;
            g_bn1[64 + tid] = bet1[tid] - mean * sc;
        }
    }
}

// ---------------- K4: out_pre = [x | bnrelu(y_pre)] @ [W1; W2] + biases ----
// BM=128, BN=128, BK=16, 512 threads (16 warps), A-dup natural layout,
// B pair-swizzled. grid = 128. Last-finishing block folds BN2 -> g_bn2.
__global__ __launch_bounds__(512) void k4_gemm(
    const float* __restrict__ x,
    const float* __restrict__ w1,  const float* __restrict__ w2,
    const float* __restrict__ b1w, const float* __restrict__ b2w,
    const float* __restrict__ gam2, const float* __restrict__ bet2,
    float* __restrict__ out)
{
    __shared__ float Asd[16][258];
    __shared__ float Bsp[16][128];
    __shared__ float s_scale[64], s_shift[64], s_bias[128];
    __shared__ float s_m[16][128], s_v[16][128];
    __shared__ bool  s_last;

    const int tid = threadIdx.x;
    const int r0  = blockIdx.x * 128;

    if (tid < 64)  { s_scale[tid] = g_bn1[tid]; s_shift[tid] = g_bn1[64 + tid]; }
    if (tid < 128) s_bias[tid] = b1w[tid] + b2w[tid];

    const int tx = tid & 15;   // col group of 8
    const int ty = tid >> 4;   // 0..31: rows ty*4..ty*4+3
    ull acc[4][4];
    #pragma unroll
    for (int i = 0; i < 4; i++)
        #pragma unroll
        for (int j = 0; j < 4; j++) acc[i][j] = 0ULL;

    for (int k0 = 0; k0 < 128; k0 += 16) {
        const bool xhalf = (k0 < 64);
        __syncthreads();
        #pragma unroll
        for (int i = tid; i < 2048; i += 512) {
            const int m = i >> 4, kk = i & 15;
            float v;
            if (xhalf) {
                v = x[(size_t)(r0 + m) * CIN + k0 + kk];
            } else {
                const int c = k0 + kk - 64;
                v = g_Y[(size_t)(r0 + m) * HID + c];
                v = fmaxf(fmaf(v, s_scale[c], s_shift[c]), 0.f);
            }
            *(float2*)&Asd[kk][2 * m] = make_float2(v, v);
        }
        #pragma unroll
        for (int i = tid; i < 2048; i += 512) {
            const int r = i >> 7, h = i & 127;
            const float v = xhalf ? w1[(k0 + r) * OUTC + h]
                                  : w2[(k0 + r - 64) * OUTC + h];
            Bsp[r][((h & 7) >> 1) * 32 + (h >> 3) * 2 + (h & 1)] = v;
        }
        __syncthreads();
        #pragma unroll
        for (int kk = 0; kk < 16; kk++) {
            const ull* ap = (const ull*)&Asd[kk][0];
            const ull* bp = (const ull*)&Bsp[kk][0];
            ull a[4], b[4];
            #pragma unroll
            for (int i = 0; i < 4; i++) a[i] = ap[ty * 4 + i];
            #pragma unroll
            for (int jp = 0; jp < 4; jp++) b[jp] = bp[jp * 16 + tx];
            #pragma unroll
            for (int i = 0; i < 4; i++)
                #pragma unroll
                for (int jp = 0; jp < 4; jp++)
                    ffma2(acc[i][jp], a[i], b[jp]);
        }
    }

    // epilogue: bias, store, BN2 partials
    float cs[8], cs2[8];
    #pragma unroll
    for (int q = 0; q < 8; q++) { cs[q] = 0.f; cs2[q] = 0.f; }
    #pragma unroll
    for (int i = 0; i < 4; i++) {
        const int r = r0 + ty * 4 + i;
        float vv[8];
        #pragma unroll
        for (int jp = 0; jp < 4; jp++) {
            const float2 v = unpk(acc[i][jp]);
            vv[jp * 2]     = v.x;
            vv[jp * 2 + 1] = v.y;
        }
        #pragma unroll
        for (int q = 0; q < 8; q++) {
            vv[q] += s_bias[tx * 8 + q];
            cs[q] += vv[q];
            cs2[q] += vv[q] * vv[q];
        }
        float* op = out + (size_t)r * OUTC + tx * 8;
        *(float4*)op       = make_float4(vv[0], vv[1], vv[2], vv[3]);
        *(float4*)(op + 4) = make_float4(vv[4], vv[5], vv[6], vv[7]);
    }
    #pragma unroll
    for (int q = 0; q < 8; q++) {
        cs[q]  += __shfl_down_sync(0xffffffffu, cs[q], 16);
        cs2[q] += __shfl_down_sync(0xffffffffu, cs2[q], 16);
    }
    const int lane = tid & 31, wrp = tid >> 5;
    if (lane < 16) {
        #pragma unroll
        for (int q = 0; q < 8; q++) {
            s_m[wrp][lane * 8 + q] = cs[q];
            s_v[wrp][lane * 8 + q] = cs2[q];
        }
    }
    __syncthreads();
    if (tid < 128) {
        float s = 0.f, s2 = 0.f;
        #pragma unroll
        for (int g = 0; g < 16; g++) { s += s_m[g][tid]; s2 += s_v[g][tid]; }
        g_part2[blockIdx.x * 128 + tid] = s;
        g_part2[16384 + blockIdx.x * 128 + tid] = s2;
    }

    // last-block-done: fold BN2 stats (k6 consumes g_bn2)
    __threadfence();
    if (tid == 0) s_last = (atomicAdd(&g_cnt2, 1) == (int)gridDim.x - 1);
    __syncthreads();
    if (s_last) {
        const int ch = tid & 127, q = tid >> 7;  // q = 0..3, 32 blocks each
        float s = 0.f, s2 = 0.f;
        #pragma unroll
        for (int b = q * 32; b < q * 32 + 32; b++) {
            s  += g_part2[b * 128 + ch];
            s2 += g_part2[16384 + b * 128 + ch];
        }
        s_m[q][ch] = s; s_v[q][ch] = s2;
        __syncthreads();
        if (tid < 128) {
            const float ss  = s_m[0][tid] + s_m[1][tid] + s_m[2][tid] + s_m[3][tid];
            const float ss2 = s_v[0][tid] + s_v[1][tid] + s_v[2][tid] + s_v[3][tid];
            const float mean = ss * (1.f / (float)N_NODES);
            const float var  = ss2 * (1.f / (float)N_NODES) - mean * mean;
            const float sc = rsqrtf(var + EPS) * gam2[tid];
            g_bn2[tid] = sc;
            g_bn2[128 + tid] = bet2[tid] - mean * sc;
        }
    }
}

// ---------------- K6: pure elementwise BN + relu ----------------
// grid = 256 blocks, 256 threads; each block handles 64 rows (2048 float4).
__global__ __launch_bounds__(256) void k6_elem(float* __restrict__ out)
{
    __shared__ float s_sc[128], s_sh[128];
    const int tid = threadIdx.x;
    if (tid < 128) { s_sc[tid] = g_bn2[tid]; s_sh[tid] = g_bn2[128 + tid]; }
    __syncthreads();

    float4* o4 = (float4*)(out + (size_t)blockIdx.x * 64 * OUTC);
    #pragma unroll
    for (int i = tid; i < 64 * 32; i += 256) {
        const int c = (i & 31) * 4;
        float4 v = o4[i];
        v.x = fmaxf(fmaf(v.x, s_sc[c + 0], s_sh[c + 0]), 0.f);
        v.y = fmaxf(fmaf(v.y, s_sc[c + 1], s_sh[c + 1]), 0.f);
        v.z = fmaxf(fmaf(v.z, s_sc[c + 2], s_sh[c + 2]), 0.f);
        v.w = fmaxf(fmaf(v.w, s_sc[c + 3], s_sh[c + 3]), 0.f);
        o4[i] = v;
    }
}

// ---------------- launcher ----------------
extern "C" void kernel_launch(void* const* d_in, const int* in_sizes, int n_in,
                              void* d_out, int out_size)
{
    const float* x   = (const float*)d_in[0];
    const float* p   = (const float*)d_in[1];
    const int*   sid = (const int*)d_in[2];
    // d_in[3] = tid_euc (implicit arange/k grouping; unused)

    int o = 4;
    if (n_in >= 16 && in_sizes[4] == 1) o = 6;

    const float* lins_W = (const float*)d_in[o];
    const float* lins_b = (const float*)d_in[o + 1];
    const float* lin1_W = (const float*)d_in[o + 2];
    const float* lin1_b = (const float*)d_in[o + 3];
    const float* lin2_W = (const float*)d_in[o + 4];
    const float* lin2_b = (const float*)d_in[o + 5];
    const float* g1     = (const float*)d_in[o + 6];
    const float* b1     = (const float*)d_in[o + 7];
    const float* g2     = (const float*)d_in[o + 8];
    const float* b2     = (const float*)d_in[o + 9];
    float* out = (float*)d_out;

    k1_edge<<<N_NODES / 4, 256>>>(x, p, sid);
    k2_gemm<<<N_NODES / 128, 512>>>(lins_W, lins_b, g1, b1);
    k4_gemm<<<N_NODES / 128, 512>>>(x, lin1_W, lin2_W, lin1_b, lin2_b, g2, b2, out);
    k6_elem<<<N_NODES / 64, 256>>>(out);
}

// round 13
// speedup vs baseline: 1.1975x; 1.1975x over previous
#include <cuda_runtime.h>
#include <cuda_bf16.h>

typedef unsigned long long ull;

// Problem constants (fixed by the dataset)
#define N_NODES 16384      // B*n = 8*2048
#define K_EDGE  16
#define CIN     64
#define HID     64
#define OUTC    128
#define L6      6
#define KV      384        // 6*64
#define EPS     1e-5f

// ---------------- scratch (device globals; no allocations) ----------------
__device__ float g_V[N_NODES * KV];        // [t][l*64+c]
__device__ float g_Cl[N_NODES * L6];       // per-target coefficient sums
__device__ float g_Y[N_NODES * HID];       // y_pre (before BN1)
__device__ float g_part1[2 * 128 * HID];   // per-k2-block BN partials (sum, sumsq)
__device__ float g_part2[2 * 128 * OUTC];  // per-k4-block BN partials
__device__ float g_bn1[2 * HID];           // folded scale/shift for BN1
__device__ float g_bn2[2 * OUTC];          // folded scale/shift for BN2
__device__ int   g_cnt1, g_cnt2;           // last-block-done counters

// ---------------- helpers ----------------
__device__ __forceinline__ void ffma2(ull& d, ull a, ull b) {
    asm("fma.rn.f32x2 %0, %1, %2, %3;" : "=l"(d) : "l"(a), "l"(b), "l"(d));
}
__device__ __forceinline__ ull swap2(ull v) {
    ull r;
    asm("{ .reg .b32 lo, hi; mov.b64 {lo, hi}, %1; mov.b64 %0, {hi, lo}; }"
        : "=l"(r) : "l"(v));
    return r;
}
__device__ __forceinline__ float2 unpk(ull v) {
    float2 r; asm("mov.b64 {%0, %1}, %2;" : "=f"(r.x), "=f"(r.y) : "l"(v)); return r;
}
__device__ __forceinline__ void cp4(void* smem_dst, const void* gsrc) {
    unsigned d = (unsigned)__cvta_generic_to_shared(smem_dst);
    asm volatile("cp.async.ca.shared.global [%0], [%1], 4;" :: "r"(d), "l"(gsrc));
}
__device__ __forceinline__ void cp_commit() { asm volatile("cp.async.commit_group;"); }
__device__ __forceinline__ void cp_wait0()  { asm volatile("cp.async.wait_group 0;" ::: "memory"); }

// ---------------- fillers: reset + nop (ncu captured index 3 = k2) ---------
__global__ void d_reset() {
    if (threadIdx.x == 0) { g_cnt1 = 0; g_cnt2 = 0; }
}
__global__ void d_nop() {}

// ---------------- K1: per-target edge phase (proven) ----------------
// grid = N_NODES/4 blocks, 256 threads (4 targets per block).
__global__ __launch_bounds__(256) void k1_edge(
    const float* __restrict__ x, const float* __restrict__ p,
    const int* __restrict__ sid)
{
    __shared__ float s_coef[4][K_EDGE][8];
    __shared__ int   s_sid[4][K_EDGE];

    const int tid  = threadIdx.x;
    const int w    = tid >> 5;
    const int lane = tid & 31;

    if (w < 4) {
        const int t   = blockIdx.x * 4 + w;
        const int j   = lane & 15;
        const bool act = lane < 16;
        const int s   = sid[t * K_EDGE + j];

        float dx = 0.f, dy = 0.f, dz = 0.f, dis = 0.f;
        if (act) {
            const float px = p[t*3+0], py = p[t*3+1], pz = p[t*3+2];
            dx = p[s*3+0] - px;
            dy = p[s*3+1] - py;
            dz = p[s*3+2] - pz;
            dis = fmaxf(sqrtf(dx*dx + dy*dy + dz*dz), 1e-16f);
            s_sid[w][j] = s;
        }
        float m = dis;
        #pragma unroll
        for (int off = 16; off; off >>= 1)
            m = fmaxf(m, __shfl_xor_sync(0xffffffffu, m, off));
        const float pr  = 1.1f * m;
        float pdv = act ? (pr - dis) * (pr - dis) : 0.f;
        float ssum = pdv;
        #pragma unroll
        for (int off = 16; off; off >>= 1)
            ssum += __shfl_xor_sync(0xffffffffu, ssum, off);

        if (act) {
            const float wgt = pdv / ssum;
            const float inv = 1.f / dis;
            const float c0 = cosf(dx * inv);
            const float c1 = cosf(dy * inv);
            const float c2 = cosf(dz * inv);
            float a[6] = {0.f, 0.f, 0.f, 0.f, 0.f, 0.f};
            a[    ((dx > 0.f) ? 1 : 0)] = c0 * c0;
            a[2 + ((dy > 0.f) ? 1 : 0)] = c1 * c1;
            a[4 + ((dz > 0.f) ? 1 : 0)] = c2 * c2;
            #pragma unroll
            for (int l = 0; l < 6; l++) s_coef[w][j][l] = wgt * a[l];
        }
    }
    __syncthreads();

    if (tid < 24) {
        const int tw = tid / 6, l = tid - tw * 6;
        float cl = 0.f;
        #pragma unroll
        for (int j = 0; j < K_EDGE; j++) cl += s_coef[tw][j][l];
        g_Cl[(blockIdx.x * 4 + tw) * L6 + l] = cl;
    }

    const int grp = tid >> 6;
    const int c   = tid & 63;
    const int t   = blockIdx.x * 4 + grp;
    const float xt = x[t * CIN + c];
    float acc[6] = {0.f, 0.f, 0.f, 0.f, 0.f, 0.f};
    #pragma unroll
    for (int j = 0; j < K_EDGE; j++) {
        const float ev = x[s_sid[grp][j] * CIN + c] - xt;
        const float4 c01 = *(const float4*)&s_coef[grp][j][0];
        const float2 c2  = *(const float2*)&s_coef[grp][j][4];
        acc[0] = fmaf(c01.x, ev, acc[0]);
        acc[1] = fmaf(c01.y, ev, acc[1]);
        acc[2] = fmaf(c01.z, ev, acc[2]);
        acc[3] = fmaf(c01.w, ev, acc[3]);
        acc[4] = fmaf(c2.x,  ev, acc[4]);
        acc[5] = fmaf(c2.y,  ev, acc[5]);
    }
    float* vp = g_V + (size_t)t * KV + c;
    #pragma unroll
    for (int l = 0; l < 6; l++) vp[l * 64] = acc[l];
}

// ---------------- K2: y_pre = V @ Wcat + Cl @ lins_b  (+ BN1 stats) --------
// BM=128, BN=64, BK=16, 256 threads, cp.async double-buffered.
// Natural-pair outer product: A rows packed (LDS.128 -> 2 row-pairs),
// B col-pairs at ull slot (j&1)*16 + (j>>1) (LDS.64 conflict-free),
// cross terms via swap2(b). Per kk: 4 LDS + 16 FFMA2. grid = 128.
__global__ __launch_bounds__(256) void k2_gemm(
    const float* __restrict__ W2,   // lins_W viewed as (384, 64)
    const float* __restrict__ lb,   // lins_b (6, 64)
    const float* __restrict__ gam1, const float* __restrict__ bet1)
{
    __shared__ float As[2][16 * 132];   // [st][kk*132 + m] natural
    __shared__ float Bf[2][16 * 68];    // [st][kk*68 + 2*slot + lane]
    __shared__ float sb[6][64];
    __shared__ float s_m[16][64], s_v[16][64];
    __shared__ bool  s_last;

    const int tid = threadIdx.x;
    const int r0  = blockIdx.x * 128;
    for (int i = tid; i < 384; i += 256) sb[i >> 6][i & 63] = lb[i];

    const int tx  = tid & 15, ty = tid >> 4;   // cols tx*4.., rows ty*8..
    const int lkk = tid & 15, lm0 = tid >> 4;  // A loader
    const int br  = tid >> 4;                  // B loader row 0..15
    const int bt  = tid & 15;                  // B loader col group (4 cols)

    // prologue: tile 0
    #pragma unroll
    for (int jj = 0; jj < 8; jj++)
        cp4(&As[0][lkk * 132 + lm0 + 16 * jj],
            &g_V[(size_t)(r0 + lm0 + 16 * jj) * KV + lkk]);
    cp_commit();
    float4 rbv = *(const float4*)&W2[br * 64 + bt * 4];
    *(float2*)&Bf[0][br * 68 + 2 * bt]      = make_float2(rbv.x, rbv.y);
    *(float2*)&Bf[0][br * 68 + 32 + 2 * bt] = make_float2(rbv.z, rbv.w);
    cp_wait0();
    __syncthreads();

    ull an[4][2], aw[4][2];
    #pragma unroll
    for (int i = 0; i < 4; i++) { an[i][0]=0; an[i][1]=0; aw[i][0]=0; aw[i][1]=0; }

    for (int s = 0; s < 24; s++) {
        const int st = s & 1;
        const bool more = (s < 23);
        if (more) {
            const int k0n = (s + 1) * 16;
            #pragma unroll
            for (int jj = 0; jj < 8; jj++)
                cp4(&As[st ^ 1][lkk * 132 + lm0 + 16 * jj],
                    &g_V[(size_t)(r0 + lm0 + 16 * jj) * KV + k0n + lkk]);
            cp_commit();
            rbv = *(const float4*)&W2[(k0n + br) * 64 + bt * 4];
        }
        #pragma unroll
        for (int kk = 0; kk < 16; kk++) {
            const float* ab = &As[st][kk * 132 + ty * 8];
            const ulonglong2 av0 = *(const ulonglong2*)ab;
            const ulonglong2 av1 = *(const ulonglong2*)(ab + 4);
            const ull* bp = (const ull*)&Bf[st][kk * 68];
            const ull b0 = bp[tx], b1 = bp[16 + tx];
            const ull w0 = swap2(b0), w1 = swap2(b1);
            ffma2(an[0][0], av0.x, b0); ffma2(aw[0][0], av0.x, w0);
            ffma2(an[0][1], av0.x, b1); ffma2(aw[0][1], av0.x, w1);
            ffma2(an[1][0], av0.y, b0); ffma2(aw[1][0], av0.y, w0);
            ffma2(an[1][1], av0.y, b1); ffma2(aw[1][1], av0.y, w1);
            ffma2(an[2][0], av1.x, b0); ffma2(aw[2][0], av1.x, w0);
            ffma2(an[2][1], av1.x, b1); ffma2(aw[2][1], av1.x, w1);
            ffma2(an[3][0], av1.y, b0); ffma2(aw[3][0], av1.y, w0);
            ffma2(an[3][1], av1.y, b1); ffma2(aw[3][1], av1.y, w1);
        }
        if (more) {
            *(float2*)&Bf[st ^ 1][br * 68 + 2 * bt]      = make_float2(rbv.x, rbv.y);
            *(float2*)&Bf[st ^ 1][br * 68 + 32 + 2 * bt] = make_float2(rbv.z, rbv.w);
            cp_wait0();
        }
        __syncthreads();
    }

    // epilogue: + Cl@lins_b, store y_pre, BN1 partials
    // pair pi: rows re=ty*8+2pi (even), re+1 (odd); cols tx*4+n:
    //  even row: n -> {an[pi][0].lo, aw[pi][0].lo, an[pi][1].lo, aw[pi][1].lo}
    //  odd  row: n -> {aw[pi][0].hi, an[pi][0].hi, aw[pi][1].hi, an[pi][1].hi}
    float cs[4] = {0.f, 0.f, 0.f, 0.f}, cs2[4] = {0.f, 0.f, 0.f, 0.f};
    #pragma unroll
    for (int pi = 0; pi < 4; pi++) {
        const int re = r0 + ty * 8 + 2 * pi;
        const float2 n0 = unpk(an[pi][0]), n1 = unpk(an[pi][1]);
        const float2 w0 = unpk(aw[pi][0]), w1 = unpk(aw[pi][1]);
        float ve[4] = {n0.x, w0.x, n1.x, w1.x};
        float vo[4] = {w0.y, n0.y, w1.y, n1.y};

        float cle[6], clo[6];
        #pragma unroll
        for (int l = 0; l < 6; l++) { cle[l] = g_Cl[re * L6 + l]; clo[l] = g_Cl[(re + 1) * L6 + l]; }

        #pragma unroll
        for (int n = 0; n < 4; n++) {
            const int h = tx * 4 + n;
            #pragma unroll
            for (int l = 0; l < 6; l++) {
                ve[n] = fmaf(cle[l], sb[l][h], ve[n]);
                vo[n] = fmaf(clo[l], sb[l][h], vo[n]);
            }
            cs[n]  += ve[n] + vo[n];
            cs2[n] += ve[n] * ve[n] + vo[n] * vo[n];
        }
        *(float4*)&g_Y[(size_t)re * HID + tx * 4] =
            make_float4(ve[0], ve[1], ve[2], ve[3]);
        *(float4*)&g_Y[(size_t)(re + 1) * HID + tx * 4] =
            make_float4(vo[0], vo[1], vo[2], vo[3]);
    }
    #pragma unroll
    for (int n = 0; n < 4; n++) {
        s_m[ty][tx * 4 + n] = cs[n];
        s_v[ty][tx * 4 + n] = cs2[n];
    }
    __syncthreads();
    if (tid < 64) {
        float s = 0.f, s2 = 0.f;
        #pragma unroll
        for (int g = 0; g < 16; g++) { s += s_m[g][tid]; s2 += s_v[g][tid]; }
        g_part1[blockIdx.x * 64 + tid] = s;
        g_part1[8192 + blockIdx.x * 64 + tid] = s2;
    }

    // last-block-done: fold BN1 stats
    __threadfence();
    if (tid == 0) s_last = (atomicAdd(&g_cnt1, 1) == (int)gridDim.x - 1);
    __syncthreads();
    if (s_last) {
        const int ch = tid & 63, q = tid >> 6;
        float s = 0.f, s2 = 0.f;
        #pragma unroll
        for (int b = q * 32; b < q * 32 + 32; b++) {
            s  += g_part1[b * 64 + ch];
            s2 += g_part1[8192 + b * 64 + ch];
        }
        s_m[q][ch] = s; s_v[q][ch] = s2;
        __syncthreads();
        if (tid < 64) {
            const float ss  = s_m[0][tid] + s_m[1][tid] + s_m[2][tid] + s_m[3][tid];
            const float ss2 = s_v[0][tid] + s_v[1][tid] + s_v[2][tid] + s_v[3][tid];
            const float mean = ss * (1.f / (float)N_NODES);
            const float var  = ss2 * (1.f / (float)N_NODES) - mean * mean;
            const float sc = rsqrtf(var + EPS) * gam1[tid];
            g_bn1[tid] = sc;
            g_bn1[64 + tid] = bet1[tid] - mean * sc;
        }
    }
}

// ---------------- K4: out_pre = [x | bnrelu(y_pre)] @ [W1; W2] + biases ----
// BM=128, BN=128, BK=16, 256 threads. Natural-pair outer product:
// A natural (LDS.128), B col-pairs at slot (j&3)*16 + (j>>2). Per kk:
// 6 LDS + 32 FFMA2. grid = 128. Last-finishing block folds BN2 -> g_bn2.
__global__ __launch_bounds__(256) void k4_gemm(
    const float* __restrict__ x,
    const float* __restrict__ w1,  const float* __restrict__ w2,
    const float* __restrict__ b1w, const float* __restrict__ b2w,
    const float* __restrict__ gam2, const float* __restrict__ bet2,
    float* __restrict__ out)
{
    __shared__ float Asn[16 * 132];
    __shared__ float Bfm[16 * 132];
    __shared__ float s_scale[64], s_shift[64], s_bias[128];
    __shared__ float s_m[16][128], s_v[16][128];
    __shared__ bool  s_last;

    const int tid = threadIdx.x;
    const int r0  = blockIdx.x * 128;

    if (tid < 64)  { s_scale[tid] = g_bn1[tid]; s_shift[tid] = g_bn1[64 + tid]; }
    if (tid < 128) s_bias[tid] = b1w[tid] + b2w[tid];

    const int tx = tid & 15;   // cols tx*8..
    const int ty = tid >> 4;   // rows ty*8..
    const int u  = tid & 31;   // B loader col group (4 cols)
    const int brow = tid >> 5; // B loader row 0..7
    const int sa = 32 * (u & 1) + (u >> 1);   // slot for cols u*4, u*4+1

    ull an[4][4], aw[4][4];
    #pragma unroll
    for (int i = 0; i < 4; i++)
        #pragma unroll
        for (int q = 0; q < 4; q++) { an[i][q] = 0ULL; aw[i][q] = 0ULL; }

    for (int k0 = 0; k0 < 128; k0 += 16) {
        const bool xhalf = (k0 < 64);
        __syncthreads();
        #pragma unroll
        for (int i = tid; i < 2048; i += 256) {
            const int m = i >> 4, kk = i & 15;
            float v;
            if (xhalf) {
                v = x[(size_t)(r0 + m) * CIN + k0 + kk];
            } else {
                const int c = k0 + kk - 64;
                v = g_Y[(size_t)(r0 + m) * HID + c];
                v = fmaxf(fmaf(v, s_scale[c], s_shift[c]), 0.f);
            }
            Asn[kk * 132 + m] = v;
        }
        #pragma unroll
        for (int jj = 0; jj < 2; jj++) {
            const int r = brow + jj * 8;
            const float* wrow = xhalf ? &w1[(k0 + r) * OUTC]
                                      : &w2[(k0 + r - 64) * OUTC];
            const float4 v = *(const float4*)&wrow[u * 4];
            *(float2*)&Bfm[r * 132 + 2 * sa]        = make_float2(v.x, v.y);
            *(float2*)&Bfm[r * 132 + 2 * (sa + 16)] = make_float2(v.z, v.w);
        }
        __syncthreads();
        #pragma unroll
        for (int kk = 0; kk < 16; kk++) {
            const float* ab = &Asn[kk * 132 + ty * 8];
            const ulonglong2 av0 = *(const ulonglong2*)ab;
            const ulonglong2 av1 = *(const ulonglong2*)(ab + 4);
            const ull a[4] = {av0.x, av0.y, av1.x, av1.y};
            const ull* bp = (const ull*)&Bfm[kk * 132];
            ull b[4], w[4];
            #pragma unroll
            for (int q = 0; q < 4; q++) { b[q] = bp[q * 16 + tx]; w[q] = swap2(b[q]); }
            #pragma unroll
            for (int i = 0; i < 4; i++)
                #pragma unroll
                for (int q = 0; q < 4; q++) {
                    ffma2(an[i][q], a[i], b[q]);
                    ffma2(aw[i][q], a[i], w[q]);
                }
        }
    }

    // epilogue: bias, store, BN2 partials
    // pair i: rows re=ty*8+2i (even), re+1 (odd); cols tx*8+n (q=n>>1):
    //  even: n even -> an[i][q].lo ; n odd -> aw[i][q].lo
    //  odd : n even -> aw[i][q].hi ; n odd -> an[i][q].hi
    float cs[8], cs2[8];
    #pragma unroll
    for (int q = 0; q < 8; q++) { cs[q] = 0.f; cs2[q] = 0.f; }
    #pragma unroll
    for (int i = 0; i < 4; i++) {
        const int re = r0 + ty * 8 + 2 * i;
        float ve[8], vo[8];
        #pragma unroll
        for (int q = 0; q < 4; q++) {
            const float2 nn = unpk(an[i][q]);
            const float2 ww = unpk(aw[i][q]);
            ve[2 * q]     = nn.x;  ve[2 * q + 1] = ww.x;
            vo[2 * q]     = ww.y;  vo[2 * q + 1] = nn.y;
        }
        #pragma unroll
        for (int n = 0; n < 8; n++) {
            const float bb = s_bias[tx * 8 + n];
            ve[n] += bb; vo[n] += bb;
            cs[n]  += ve[n] + vo[n];
            cs2[n] += ve[n] * ve[n] + vo[n] * vo[n];
        }
        float* oe = out + (size_t)re * OUTC + tx * 8;
        float* oo = out + (size_t)(re + 1) * OUTC + tx * 8;
        *(float4*)oe       = make_float4(ve[0], ve[1], ve[2], ve[3]);
        *(float4*)(oe + 4) = make_float4(ve[4], ve[5], ve[6], ve[7]);
        *(float4*)oo       = make_float4(vo[0], vo[1], vo[2], vo[3]);
        *(float4*)(oo + 4) = make_float4(vo[4], vo[5], vo[6], vo[7]);
    }
    #pragma unroll
    for (int q = 0; q < 8; q++) {
        s_m[ty][tx * 8 + q] = cs[q];
        s_v[ty][tx * 8 + q] = cs2[q];
    }
    __syncthreads();
    if (tid < 128) {
        float s = 0.f, s2 = 0.f;
        #pragma unroll
        for (int g = 0; g < 16; g++) { s += s_m[g][tid]; s2 += s_v[g][tid]; }
        g_part2[blockIdx.x * 128 + tid] = s;
        g_part2[16384 + blockIdx.x * 128 + tid] = s2;
    }

    // last-block-done: fold BN2 stats (k6 consumes g_bn2)
    __threadfence();
    if (tid == 0) s_last = (atomicAdd(&g_cnt2, 1) == (int)gridDim.x - 1);
    __syncthreads();
    if (s_last) {
        const int ch = tid & 127, q = tid >> 7;
        float s = 0.f, s2 = 0.f;
        #pragma unroll
        for (int b = q * 64; b < q * 64 + 64; b++) {
            s  += g_part2[b * 128 + ch];
            s2 += g_part2[16384 + b * 128 + ch];
        }
        s_m[q][ch] = s; s_v[q][ch] = s2;
        __syncthreads();
        if (tid < 128) {
            const float ss  = s_m[0][tid] + s_m[1][tid];
            const float ss2 = s_v[0][tid] + s_v[1][tid];
            const float mean = ss * (1.f / (float)N_NODES);
            const float var  = ss2 * (1.f / (float)N_NODES) - mean * mean;
            const float sc = rsqrtf(var + EPS) * gam2[tid];
            g_bn2[tid] = sc;
            g_bn2[128 + tid] = bet2[tid] - mean * sc;
        }
    }
}

// ---------------- K6: pure elementwise BN + relu ----------------
// grid = 256 blocks, 256 threads; each block handles 64 rows (2048 float4).
__global__ __launch_bounds__(256) void k6_elem(float* __restrict__ out)
{
    __shared__ float s_sc[128], s_sh[128];
    const int tid = threadIdx.x;
    if (tid < 128) { s_sc[tid] = g_bn2[tid]; s_sh[tid] = g_bn2[128 + tid]; }
    __syncthreads();

    float4* o4 = (float4*)(out + (size_t)blockIdx.x * 64 * OUTC);
    #pragma unroll
    for (int i = tid; i < 64 * 32; i += 256) {
        const int c = (i & 31) * 4;
        float4 v = o4[i];
        v.x = fmaxf(fmaf(v.x, s_sc[c + 0], s_sh[c + 0]), 0.f);
        v.y = fmaxf(fmaf(v.y, s_sc[c + 1], s_sh[c + 1]), 0.f);
        v.z = fmaxf(fmaf(v.z, s_sc[c + 2], s_sh[c + 2]), 0.f);
        v.w = fmaxf(fmaf(v.w, s_sc[c + 3], s_sh[c + 3]), 0.f);
        o4[i] = v;
    }
}

// ---------------- launcher ----------------
extern "C" void kernel_launch(void* const* d_in, const int* in_sizes, int n_in,
                              void* d_out, int out_size)
{
    const float* x   = (const float*)d_in[0];
    const float* p   = (const float*)d_in[1];
    const int*   sid = (const int*)d_in[2];
    // d_in[3] = tid_euc (implicit arange/k grouping; unused)

    int o = 4;
    if (n_in >= 16 && in_sizes[4] == 1) o = 6;

    const float* lins_W = (const float*)d_in[o];
    const float* lins_b = (const float*)d_in[o + 1];
    const float* lin1_W = (const float*)d_in[o + 2];
    const float* lin1_b = (const float*)d_in[o + 3];
    const float* lin2_W = (const float*)d_in[o + 4];
    const float* lin2_b = (const float*)d_in[o + 5];
    const float* g1     = (const float*)d_in[o + 6];
    const float* b1     = (const float*)d_in[o + 7];
    const float* g2     = (const float*)d_in[o + 8];
    const float* b2     = (const float*)d_in[o + 9];
    float* out = (float*)d_out;

    d_reset<<<1, 32>>>();
    d_nop<<<1, 32>>>();
    k1_edge<<<N_NODES / 4, 256>>>(x, p, sid);
    k2_gemm<<<N_NODES / 128, 256>>>(lins_W, lins_b, g1, b1);
    k4_gemm<<<N_NODES / 128, 256>>>(x, lin1_W, lin2_W, lin1_b, lin2_b, g2, b2, out);
    k6_elem<<<N_NODES / 64, 256>>>(out);
}

// round 14
// speedup vs baseline: 1.2318x; 1.0287x over previous
#include <cuda_runtime.h>
#include <cuda_bf16.h>

typedef unsigned long long ull;

// Problem constants (fixed by the dataset)
#define N_NODES 16384      // B*n = 8*2048
#define K_EDGE  16
#define CIN     64
#define HID     64
#define OUTC    128
#define L6      6
#define KV      384        // 6*64
#define EPS     1e-5f

// ---------------- scratch (device globals; no allocations) ----------------
__device__ float g_V[N_NODES * KV];        // [t][l*64+c]
__device__ float g_Cl[N_NODES * L6];       // per-target coefficient sums
__device__ float g_Y[N_NODES * HID];       // y_pre (before BN1)
__device__ float g_part1[2 * 128 * HID];   // per-k2-block BN partials (sum, sumsq)
__device__ float g_part2[2 * 128 * OUTC];  // per-k4-block BN partials
__device__ float g_bn1[2 * HID];           // folded scale/shift for BN1
__device__ float g_bn2[2 * OUTC];          // folded scale/shift for BN2
__device__ int   g_cnt1, g_cnt2;           // last-block-done counters

// ---------------- helpers ----------------
__device__ __forceinline__ void ffma2(ull& d, ull a, ull b) {
    asm("fma.rn.f32x2 %0, %1, %2, %3;" : "=l"(d) : "l"(a), "l"(b), "l"(d));
}
__device__ __forceinline__ ull swap2(ull v) {
    ull r;
    asm("{ .reg .b32 lo, hi; mov.b64 {lo, hi}, %1; mov.b64 %0, {hi, lo}; }"
        : "=l"(r) : "l"(v));
    return r;
}
__device__ __forceinline__ float2 unpk(ull v) {
    float2 r; asm("mov.b64 {%0, %1}, %2;" : "=f"(r.x), "=f"(r.y) : "l"(v)); return r;
}
__device__ __forceinline__ void cp4(void* smem_dst, const void* gsrc) {
    unsigned d = (unsigned)__cvta_generic_to_shared(smem_dst);
    asm volatile("cp.async.ca.shared.global [%0], [%1], 4;" :: "r"(d), "l"(gsrc));
}
__device__ __forceinline__ void cp8(void* smem_dst, const void* gsrc) {
    unsigned d = (unsigned)__cvta_generic_to_shared(smem_dst);
    asm volatile("cp.async.ca.shared.global [%0], [%1], 8;" :: "r"(d), "l"(gsrc));
}
__device__ __forceinline__ void cp_commit() { asm volatile("cp.async.commit_group;"); }
__device__ __forceinline__ void cp_wait1()  { asm volatile("cp.async.wait_group 1;" ::: "memory"); }

// ---------------- fillers: reset + nop (ncu captured index 3 = k2) ---------
__global__ void d_reset() {
    if (threadIdx.x == 0) { g_cnt1 = 0; g_cnt2 = 0; }
}
__global__ void d_nop() {}

// ---------------- K1: per-target edge phase (proven) ----------------
// grid = N_NODES/4 blocks, 256 threads (4 targets per block).
__global__ __launch_bounds__(256) void k1_edge(
    const float* __restrict__ x, const float* __restrict__ p,
    const int* __restrict__ sid)
{
    __shared__ float s_coef[4][K_EDGE][8];
    __shared__ int   s_sid[4][K_EDGE];

    const int tid  = threadIdx.x;
    const int w    = tid >> 5;
    const int lane = tid & 31;

    if (w < 4) {
        const int t   = blockIdx.x * 4 + w;
        const int j   = lane & 15;
        const bool act = lane < 16;
        const int s   = sid[t * K_EDGE + j];

        float dx = 0.f, dy = 0.f, dz = 0.f, dis = 0.f;
        if (act) {
            const float px = p[t*3+0], py = p[t*3+1], pz = p[t*3+2];
            dx = p[s*3+0] - px;
            dy = p[s*3+1] - py;
            dz = p[s*3+2] - pz;
            dis = fmaxf(sqrtf(dx*dx + dy*dy + dz*dz), 1e-16f);
            s_sid[w][j] = s;
        }
        float m = dis;
        #pragma unroll
        for (int off = 16; off; off >>= 1)
            m = fmaxf(m, __shfl_xor_sync(0xffffffffu, m, off));
        const float pr  = 1.1f * m;
        float pdv = act ? (pr - dis) * (pr - dis) : 0.f;
        float ssum = pdv;
        #pragma unroll
        for (int off = 16; off; off >>= 1)
            ssum += __shfl_xor_sync(0xffffffffu, ssum, off);

        if (act) {
            const float wgt = pdv / ssum;
            const float inv = 1.f / dis;
            const float c0 = cosf(dx * inv);
            const float c1 = cosf(dy * inv);
            const float c2 = cosf(dz * inv);
            float a[6] = {0.f, 0.f, 0.f, 0.f, 0.f, 0.f};
            a[    ((dx > 0.f) ? 1 : 0)] = c0 * c0;
            a[2 + ((dy > 0.f) ? 1 : 0)] = c1 * c1;
            a[4 + ((dz > 0.f) ? 1 : 0)] = c2 * c2;
            #pragma unroll
            for (int l = 0; l < 6; l++) s_coef[w][j][l] = wgt * a[l];
        }
    }
    __syncthreads();

    if (tid < 24) {
        const int tw = tid / 6, l = tid - tw * 6;
        float cl = 0.f;
        #pragma unroll
        for (int j = 0; j < K_EDGE; j++) cl += s_coef[tw][j][l];
        g_Cl[(blockIdx.x * 4 + tw) * L6 + l] = cl;
    }

    const int grp = tid >> 6;
    const int c   = tid & 63;
    const int t   = blockIdx.x * 4 + grp;
    const float xt = x[t * CIN + c];
    float acc[6] = {0.f, 0.f, 0.f, 0.f, 0.f, 0.f};
    #pragma unroll
    for (int j = 0; j < K_EDGE; j++) {
        const float ev = x[s_sid[grp][j] * CIN + c] - xt;
        const float4 c01 = *(const float4*)&s_coef[grp][j][0];
        const float2 c2  = *(const float2*)&s_coef[grp][j][4];
        acc[0] = fmaf(c01.x, ev, acc[0]);
        acc[1] = fmaf(c01.y, ev, acc[1]);
        acc[2] = fmaf(c01.z, ev, acc[2]);
        acc[3] = fmaf(c01.w, ev, acc[3]);
        acc[4] = fmaf(c2.x,  ev, acc[4]);
        acc[5] = fmaf(c2.y,  ev, acc[5]);
    }
    float* vp = g_V + (size_t)t * KV + c;
    #pragma unroll
    for (int l = 0; l < 6; l++) vp[l * 64] = acc[l];
}

// ---------------- K2: y_pre = V @ Wcat + Cl @ lins_b  (+ BN1 stats) --------
// BM=128, BN=64, BK=16, 256 threads, 3-STAGE cp.async pipeline (A cp4,
// B cp8 into pair-swizzle slots), wait_group 1 -> each tile's loads get a
// full compute-step of slack. Natural-pair outer product inner loop
// (4 LDS + 16 FFMA2 per kk). grid = 128.
__global__ __launch_bounds__(256) void k2_gemm(
    const float* __restrict__ W2,   // lins_W viewed as (384, 64)
    const float* __restrict__ lb,   // lins_b (6, 64)
    const float* __restrict__ gam1, const float* __restrict__ bet1)
{
    __shared__ __align__(16) float As[3][16 * 132];   // natural [kk][m]
    __shared__ __align__(16) float Bf[3][16 * 68];    // pair slots (j&1)*16+(j>>1)
    __shared__ float sb[6][64];
    __shared__ float s_m[16][64], s_v[16][64];
    __shared__ bool  s_last;

    const int tid = threadIdx.x;
    const int r0  = blockIdx.x * 128;
    for (int i = tid; i < 384; i += 256) sb[i >> 6][i & 63] = lb[i];

    const int tx  = tid & 15, ty = tid >> 4;   // cols tx*4.., rows ty*8..
    const int lkk = tid & 15, lm0 = tid >> 4;  // A loader
    const int br  = tid >> 4, bt = tid & 15;   // B loader: row br, cols 4bt..

    // issue all loads for tile t into stage st, commit as one group
    auto load_tile = [&](int t, int st) {
        const int k0 = t * 16;
        #pragma unroll
        for (int jj = 0; jj < 8; jj++)
            cp4(&As[st][lkk * 132 + lm0 + 16 * jj],
                &g_V[(size_t)(r0 + lm0 + 16 * jj) * KV + k0 + lkk]);
        const float* wsrc = &W2[(k0 + br) * 64 + 4 * bt];
        cp8(&Bf[st][br * 68 + 2 * bt],      wsrc);
        cp8(&Bf[st][br * 68 + 32 + 2 * bt], wsrc + 2);
        cp_commit();
    };

    load_tile(0, 0);
    load_tile(1, 1);
    cp_wait1();          // tile 0 complete
    __syncthreads();

    ull an[4][2], aw[4][2];
    #pragma unroll
    for (int i = 0; i < 4; i++) { an[i][0]=0; an[i][1]=0; aw[i][0]=0; aw[i][1]=0; }

    for (int s = 0; s < 24; s++) {
        const int st = s % 3;
        if (s + 2 < 24) load_tile(s + 2, (s + 2) % 3);
        else            cp_commit();     // empty group keeps pending-count uniform

        #pragma unroll
        for (int kk = 0; kk < 16; kk++) {
            const float* ab = &As[st][kk * 132 + ty * 8];
            const ulonglong2 av0 = *(const ulonglong2*)ab;
            const ulonglong2 av1 = *(const ulonglong2*)(ab + 4);
            const ull* bp = (const ull*)&Bf[st][kk * 68];
            const ull b0 = bp[tx], b1 = bp[16 + tx];
            const ull w0 = swap2(b0), w1 = swap2(b1);
            ffma2(an[0][0], av0.x, b0); ffma2(aw[0][0], av0.x, w0);
            ffma2(an[0][1], av0.x, b1); ffma2(aw[0][1], av0.x, w1);
            ffma2(an[1][0], av0.y, b0); ffma2(aw[1][0], av0.y, w0);
            ffma2(an[1][1], av0.y, b1); ffma2(aw[1][1], av0.y, w1);
            ffma2(an[2][0], av1.x, b0); ffma2(aw[2][0], av1.x, w0);
            ffma2(an[2][1], av1.x, b1); ffma2(aw[2][1], av1.x, w1);
            ffma2(an[3][0], av1.y, b0); ffma2(aw[3][0], av1.y, w0);
            ffma2(an[3][1], av1.y, b1); ffma2(aw[3][1], av1.y, w1);
        }
        cp_wait1();      // next tile complete; current+2 still in flight
        __syncthreads();
    }

    // epilogue: + Cl@lins_b, store y_pre, BN1 partials
    // pair pi: rows re=ty*8+2pi (even), re+1 (odd); cols tx*4+n:
    //  even row: n -> {an[pi][0].lo, aw[pi][0].lo, an[pi][1].lo, aw[pi][1].lo}
    //  odd  row: n -> {aw[pi][0].hi, an[pi][0].hi, aw[pi][1].hi, an[pi][1].hi}
    float cs[4] = {0.f, 0.f, 0.f, 0.f}, cs2[4] = {0.f, 0.f, 0.f, 0.f};
    #pragma unroll
    for (int pi = 0; pi < 4; pi++) {
        const int re = r0 + ty * 8 + 2 * pi;
        const float2 n0 = unpk(an[pi][0]), n1 = unpk(an[pi][1]);
        const float2 w0 = unpk(aw[pi][0]), w1 = unpk(aw[pi][1]);
        float ve[4] = {n0.x, w0.x, n1.x, w1.x};
        float vo[4] = {w0.y, n0.y, w1.y, n1.y};

        float cle[6], clo[6];
        #pragma unroll
        for (int l = 0; l < 6; l++) { cle[l] = g_Cl[re * L6 + l]; clo[l] = g_Cl[(re + 1) * L6 + l]; }

        #pragma unroll
        for (int n = 0; n < 4; n++) {
            const int h = tx * 4 + n;
            #pragma unroll
            for (int l = 0; l < 6; l++) {
                ve[n] = fmaf(cle[l], sb[l][h], ve[n]);
                vo[n] = fmaf(clo[l], sb[l][h], vo[n]);
            }
            cs[n]  += ve[n] + vo[n];
            cs2[n] += ve[n] * ve[n] + vo[n] * vo[n];
        }
        *(float4*)&g_Y[(size_t)re * HID + tx * 4] =
            make_float4(ve[0], ve[1], ve[2], ve[3]);
        *(float4*)&g_Y[(size_t)(re + 1) * HID + tx * 4] =
            make_float4(vo[0], vo[1], vo[2], vo[3]);
    }
    #pragma unroll
    for (int n = 0; n < 4; n++) {
        s_m[ty][tx * 4 + n] = cs[n];
        s_v[ty][tx * 4 + n] = cs2[n];
    }
    __syncthreads();
    if (tid < 64) {
        float s = 0.f, s2 = 0.f;
        #pragma unroll
        for (int g = 0; g < 16; g++) { s += s_m[g][tid]; s2 += s_v[g][tid]; }
        g_part1[blockIdx.x * 64 + tid] = s;
        g_part1[8192 + blockIdx.x * 64 + tid] = s2;
    }

    // last-block-done: fold BN1 stats
    __threadfence();
    if (tid == 0) s_last = (atomicAdd(&g_cnt1, 1) == (int)gridDim.x - 1);
    __syncthreads();
    if (s_last) {
        const int ch = tid & 63, q = tid >> 6;
        float s = 0.f, s2 = 0.f;
        #pragma unroll
        for (int b = q * 32; b < q * 32 + 32; b++) {
            s  += g_part1[b * 64 + ch];
            s2 += g_part1[8192 + b * 64 + ch];
        }
        s_m[q][ch] = s; s_v[q][ch] = s2;
        __syncthreads();
        if (tid < 64) {
            const float ss  = s_m[0][tid] + s_m[1][tid] + s_m[2][tid] + s_m[3][tid];
            const float ss2 = s_v[0][tid] + s_v[1][tid] + s_v[2][tid] + s_v[3][tid];
            const float mean = ss * (1.f / (float)N_NODES);
            const float var  = ss2 * (1.f / (float)N_NODES) - mean * mean;
            const float sc = rsqrtf(var + EPS) * gam1[tid];
            g_bn1[tid] = sc;
            g_bn1[64 + tid] = bet1[tid] - mean * sc;
        }
    }
}

// ---------------- K4: out_pre = [x | bnrelu(y_pre)] @ [W1; W2] + biases ----
// (R13-proven) BM=128, BN=128, BK=16, 256 threads. Natural-pair outer
// product. grid = 128. Last-finishing block folds BN2 -> g_bn2.
__global__ __launch_bounds__(256) void k4_gemm(
    const float* __restrict__ x,
    const float* __restrict__ w1,  const float* __restrict__ w2,
    const float* __restrict__ b1w, const float* __restrict__ b2w,
    const float* __restrict__ gam2, const float* __restrict__ bet2,
    float* __restrict__ out)
{
    __shared__ __align__(16) float Asn[16 * 132];
    __shared__ __align__(16) float Bfm[16 * 132];
    __shared__ float s_scale[64], s_shift[64], s_bias[128];
    __shared__ float s_m[16][128], s_v[16][128];
    __shared__ bool  s_last;

    const int tid = threadIdx.x;
    const int r0  = blockIdx.x * 128;

    if (tid < 64)  { s_scale[tid] = g_bn1[tid]; s_shift[tid] = g_bn1[64 + tid]; }
    if (tid < 128) s_bias[tid] = b1w[tid] + b2w[tid];

    const int tx = tid & 15;   // cols tx*8..
    const int ty = tid >> 4;   // rows ty*8..
    const int u  = tid & 31;   // B loader col group (4 cols)
    const int brow = tid >> 5; // B loader row 0..7
    const int sa = 32 * (u & 1) + (u >> 1);   // slot for cols u*4, u*4+1

    ull an[4][4], aw[4][4];
    #pragma unroll
    for (int i = 0; i < 4; i++)
        #pragma unroll
        for (int q = 0; q < 4; q++) { an[i][q] = 0ULL; aw[i][q] = 0ULL; }

    for (int k0 = 0; k0 < 128; k0 += 16) {
        const bool xhalf = (k0 < 64);
        __syncthreads();
        #pragma unroll
        for (int i = tid; i < 2048; i += 256) {
            const int m = i >> 4, kk = i & 15;
            float v;
            if (xhalf) {
                v = x[(size_t)(r0 + m) * CIN + k0 + kk];
            } else {
                const int c = k0 + kk - 64;
                v = g_Y[(size_t)(r0 + m) * HID + c];
                v = fmaxf(fmaf(v, s_scale[c], s_shift[c]), 0.f);
            }
            Asn[kk * 132 + m] = v;
        }
        #pragma unroll
        for (int jj = 0; jj < 2; jj++) {
            const int r = brow + jj * 8;
            const float* wrow = xhalf ? &w1[(k0 + r) * OUTC]
                                      : &w2[(k0 + r - 64) * OUTC];
            const float4 v = *(const float4*)&wrow[u * 4];
            *(float2*)&Bfm[r * 132 + 2 * sa]        = make_float2(v.x, v.y);
            *(float2*)&Bfm[r * 132 + 2 * (sa + 16)] = make_float2(v.z, v.w);
        }
        __syncthreads();
        #pragma unroll
        for (int kk = 0; kk < 16; kk++) {
            const float* ab = &Asn[kk * 132 + ty * 8];
            const ulonglong2 av0 = *(const ulonglong2*)ab;
            const ulonglong2 av1 = *(const ulonglong2*)(ab + 4);
            const ull a[4] = {av0.x, av0.y, av1.x, av1.y};
            const ull* bp = (const ull*)&Bfm[kk * 132];
            ull b[4], w[4];
            #pragma unroll
            for (int q = 0; q < 4; q++) { b[q] = bp[q * 16 + tx]; w[q] = swap2(b[q]); }
            #pragma unroll
            for (int i = 0; i < 4; i++)
                #pragma unroll
                for (int q = 0; q < 4; q++) {
                    ffma2(an[i][q], a[i], b[q]);
                    ffma2(aw[i][q], a[i], w[q]);
                }
        }
    }

    // epilogue: bias, store, BN2 partials
    float cs[8], cs2[8];
    #pragma unroll
    for (int q = 0; q < 8; q++) { cs[q] = 0.f; cs2[q] = 0.f; }
    #pragma unroll
    for (int i = 0; i < 4; i++) {
        const int re = r0 + ty * 8 + 2 * i;
        float ve[8], vo[8];
        #pragma unroll
        for (int q = 0; q < 4; q++) {
            const float2 nn = unpk(an[i][q]);
            const float2 ww = unpk(aw[i][q]);
            ve[2 * q]     = nn.x;  ve[2 * q + 1] = ww.x;
            vo[2 * q]     = ww.y;  vo[2 * q + 1] = nn.y;
        }
        #pragma unroll
        for (int n = 0; n < 8; n++) {
            const float bb = s_bias[tx * 8 + n];
            ve[n] += bb; vo[n] += bb;
            cs[n]  += ve[n] + vo[n];
            cs2[n] += ve[n] * ve[n] + vo[n] * vo[n];
        }
        float* oe = out + (size_t)re * OUTC + tx * 8;
        float* oo = out + (size_t)(re + 1) * OUTC + tx * 8;
        *(float4*)oe       = make_float4(ve[0], ve[1], ve[2], ve[3]);
        *(float4*)(oe + 4) = make_float4(ve[4], ve[5], ve[6], ve[7]);
        *(float4*)oo       = make_float4(vo[0], vo[1], vo[2], vo[3]);
        *(float4*)(oo + 4) = make_float4(vo[4], vo[5], vo[6], vo[7]);
    }
    #pragma unroll
    for (int q = 0; q < 8; q++) {
        s_m[ty][tx * 8 + q] = cs[q];
        s_v[ty][tx * 8 + q] = cs2[q];
    }
    __syncthreads();
    if (tid < 128) {
        float s = 0.f, s2 = 0.f;
        #pragma unroll
        for (int g = 0; g < 16; g++) { s += s_m[g][tid]; s2 += s_v[g][tid]; }
        g_part2[blockIdx.x * 128 + tid] = s;
        g_part2[16384 + blockIdx.x * 128 + tid] = s2;
    }

    // last-block-done: fold BN2 stats (k6 consumes g_bn2)
    __threadfence();
    if (tid == 0) s_last = (atomicAdd(&g_cnt2, 1) == (int)gridDim.x - 1);
    __syncthreads();
    if (s_last) {
        const int ch = tid & 127, q = tid >> 7;
        float s = 0.f, s2 = 0.f;
        #pragma unroll
        for (int b = q * 64; b < q * 64 + 64; b++) {
            s  += g_part2[b * 128 + ch];
            s2 += g_part2[16384 + b * 128 + ch];
        }
        s_m[q][ch] = s; s_v[q][ch] = s2;
        __syncthreads();
        if (tid < 128) {
            const float ss  = s_m[0][tid] + s_m[1][tid];
            const float ss2 = s_v[0][tid] + s_v[1][tid];
            const float mean = ss * (1.f / (float)N_NODES);
            const float var  = ss2 * (1.f / (float)N_NODES) - mean * mean;
            const float sc = rsqrtf(var + EPS) * gam2[tid];
            g_bn2[tid] = sc;
            g_bn2[128 + tid] = bet2[tid] - mean * sc;
        }
    }
}

// ---------------- K6: pure elementwise BN + relu ----------------
// grid = 256 blocks, 256 threads; each block handles 64 rows (2048 float4).
__global__ __launch_bounds__(256) void k6_elem(float* __restrict__ out)
{
    __shared__ float s_sc[128], s_sh[128];
    const int tid = threadIdx.x;
    if (tid < 128) { s_sc[tid] = g_bn2[tid]; s_sh[tid] = g_bn2[128 + tid]; }
    __syncthreads();

    float4* o4 = (float4*)(out + (size_t)blockIdx.x * 64 * OUTC);
    #pragma unroll
    for (int i = tid; i < 64 * 32; i += 256) {
        const int c = (i & 31) * 4;
        float4 v = o4[i];
        v.x = fmaxf(fmaf(v.x, s_sc[c + 0], s_sh[c + 0]), 0.f);
        v.y = fmaxf(fmaf(v.y, s_sc[c + 1], s_sh[c + 1]), 0.f);
        v.z = fmaxf(fmaf(v.z, s_sc[c + 2], s_sh[c + 2]), 0.f);
        v.w = fmaxf(fmaf(v.w, s_sc[c + 3], s_sh[c + 3]), 0.f);
        o4[i] = v;
    }
}

// ---------------- launcher ----------------
extern "C" void kernel_launch(void* const* d_in, const int* in_sizes, int n_in,
                              void* d_out, int out_size)
{
    const float* x   = (const float*)d_in[0];
    const float* p   = (const float*)d_in[1];
    const int*   sid = (const int*)d_in[2];
    // d_in[3] = tid_euc (implicit arange/k grouping; unused)

    int o = 4;
    if (n_in >= 16 && in_sizes[4] == 1) o = 6;

    const float* lins_W = (const float*)d_in[o];
    const float* lins_b = (const float*)d_in[o + 1];
    const float* lin1_W = (const float*)d_in[o + 2];
    const float* lin1_b = (const float*)d_in[o + 3];
    const float* lin2_W = (const float*)d_in[o + 4];
    const float* lin2_b = (const float*)d_in[o + 5];
    const float* g1     = (const float*)d_in[o + 6];
    const float* b1     = (const float*)d_in[o + 7];
    const float* g2     = (const float*)d_in[o + 8];
    const float* b2     = (const float*)d_in[o + 9];
    float* out = (float*)d_out;

    d_reset<<<1, 32>>>();
    d_nop<<<1, 32>>>();
    k1_edge<<<N_NODES / 4, 256>>>(x, p, sid);
    k2_gemm<<<N_NODES / 128, 256>>>(lins_W, lins_b, g1, b1);
    k4_gemm<<<N_NODES / 128, 256>>>(x, lin1_W, lin2_W, lin1_b, lin2_b, g2, b2, out);
    k6_elem<<<N_NODES / 64, 256>>>(out);
}